// round 16
// baseline (speedup 1.0000x reference)
#include <cuda_runtime.h>
#include <cuda_bf16.h>
#include <cstdint>

#define D 256
#define SS 20000
#define SEG_PER_CTA 64       // segments pooled per CTA == GEMM M-tile
#define DEPTH 4              // cp.async rows in flight per warp
#define RING  5              // ring slots (1KB each) per warp

// smem layout (dynamic):
//   [0, 64KB)            A tile: 64 pooled rows x 256 f32 (1KB/row)
//   [64KB, 64KB+40KB)    pool phase: 8 warps x RING x 1KB rings
//                        gemm phase (aliased): B double buffer 2 x 16KB
#define A_BYTES   (SEG_PER_CTA * 1024)
#define RING_OFF  A_BYTES
#define SMEM_DYN  (A_BYTES + 8 * RING * 1024)   // 104 KB -> 2 CTAs/SM

__device__ int g_segstart[SS + 1];

// ---------------------------------------------------------------------------
// Kernel 1: segment offsets from sorted index.
// ---------------------------------------------------------------------------
__global__ void seg_offsets_kernel(const int* __restrict__ index, int n) {
    int i = blockIdx.x * blockDim.x + threadIdx.x;
    if (i >= n) return;
    int cur = index[i];
    if (i == 0) {
        for (int s = 0; s <= cur; ++s) g_segstart[s] = 0;
    } else {
        int prev = index[i - 1];
        if (prev != cur)
            for (int s = prev + 1; s <= cur; ++s) g_segstart[s] = i;
    }
    if (i == n - 1) {
        for (int s = cur + 1; s <= SS; ++s) g_segstart[s] = n;
    }
}

// ---------------------------------------------------------------------------
// Fused kernel: pool 64 segments into smem, then GEMM the 64x256 tile.
// ---------------------------------------------------------------------------
#define FMA_F32X2(acc, a, b) \
    asm("fma.rn.f32x2 %0, %1, %2, %3;" : "=l"(acc) : "l"(a), "l"(b), "l"(acc))
#define PACK_DUP_F32X2(out, v) \
    asm("mov.b64 %0, {%1, %1};" : "=l"(out) : "r"(__float_as_uint(v)))
#define UNPACK_F32X2(lo, hi, in) \
    asm("mov.b64 {%0, %1}, %2;" : "=r"(lo), "=r"(hi) : "l"(in))

__global__ void __launch_bounds__(256, 2) fused_kernel(
    const float* __restrict__ x, const float* __restrict__ w,
    const float* __restrict__ Wg, const float* __restrict__ bg,
    const float* __restrict__ Wm, const float* __restrict__ bm,
    const float* __restrict__ p, float* __restrict__ out)
{
    extern __shared__ char smem_raw[];
    __shared__ float s_gsum[SEG_PER_CTA];

    float* As = reinterpret_cast<float*>(smem_raw);
    const int warp = threadIdx.x >> 5, lane = threadIdx.x & 31;
    const int t = threadIdx.x;
    const int seg0 = blockIdx.x * SEG_PER_CTA;

    uint32_t smem_u32;
    asm("{ .reg .u64 tt; cvta.to.shared.u64 tt, %1; cvt.u32.u64 %0, tt; }"
        : "=r"(smem_u32) : "l"(smem_raw));
    const uint32_t ring_base = smem_u32 + RING_OFF + warp * (RING * 1024);

    // XOR swizzle within a 1KB row slot: conflict-free 32B/lane ld/st
    const uint32_t bl = lane * 32u;
    const uint32_t bh = bl + 16u;
    const uint32_t off_lo = bl ^ (((bl >> 7) & 1u) << 4);
    const uint32_t off_hi = bh ^ (((bh >> 7) & 1u) << 4);

    const float4 wg0 = *reinterpret_cast<const float4*>(Wg + lane * 8);
    const float4 wg1 = *reinterpret_cast<const float4*>(Wg + lane * 8 + 4);
    const float bgv = bg[0];
    const float pv  = p[0];

    // ================= Phase 1: pool 8 segments per warp =================
    for (int i = 0; i < 8; ++i) {
        const int s  = seg0 + warp * 8 + i;
        const int lr = warp * 8 + i;                  // local A row
        if (s >= SS) break;

        const int lo  = g_segstart[s];
        const int cnt = g_segstart[s + 1] - lo;
        float* arow = As + lr * D + lane * 8;

        if (cnt == 0) {
            float4 z = make_float4(0.f, 0.f, 0.f, 0.f);
            *reinterpret_cast<float4*>(arow)     = z;
            *reinterpret_cast<float4*>(arow + 4) = z;
            if (lane == 0) s_gsum[lr] = 0.f;
            continue;
        }

        const char* src_base = reinterpret_cast<const char*>(x)
                             + (size_t)lo * 1024 + lane * 32;
        const int last = cnt - 1;

        // drain previous segment's tail groups before reusing ring slots
        asm volatile("cp.async.wait_group 0;" ::: "memory");

        #pragma unroll
        for (int j = 0; j < DEPTH; ++j) {
            const int jj = (j <= last) ? j : last;
            const uint32_t dst = ring_base + j * 1024;
            const char* src = src_base + (size_t)jj * 1024;
            asm volatile(
                "cp.async.cg.shared.global [%0], [%2], 16;\n\t"
                "cp.async.cg.shared.global [%1], [%3], 16;\n\t"
                "cp.async.commit_group;\n\t"
                :: "r"(dst + off_lo), "r"(dst + off_hi), "l"(src), "l"(src + 16));
        }

        float m = -3.4e38f, dnm = 0.f;
        float acc[8] = {0.f, 0.f, 0.f, 0.f, 0.f, 0.f, 0.f, 0.f};
        float wc = w[lo];

        int slot_r = 0, slot_i = DEPTH;
        for (int r = 0; r < cnt; ++r) {
            const float wn = (r < last) ? w[lo + r + 1] : wc;

            asm volatile("cp.async.wait_group %0;" :: "n"(DEPTH - 1) : "memory");

            const uint32_t sa = ring_base + slot_r * 1024;
            float4 c0, c1;
            asm volatile("ld.shared.v4.f32 {%0,%1,%2,%3}, [%4];"
                : "=f"(c0.x), "=f"(c0.y), "=f"(c0.z), "=f"(c0.w)
                : "r"(sa + off_lo));
            asm volatile("ld.shared.v4.f32 {%0,%1,%2,%3}, [%4];"
                : "=f"(c1.x), "=f"(c1.y), "=f"(c1.z), "=f"(c1.w)
                : "r"(sa + off_hi));

            {   // issue row r+DEPTH (clamped -> group never empty)
                const int j  = r + DEPTH;
                const int jj = (j <= last) ? j : last;
                const uint32_t dst = ring_base + slot_i * 1024;
                const char* src = src_base + (size_t)jj * 1024;
                asm volatile(
                    "cp.async.cg.shared.global [%0], [%2], 16;\n\t"
                    "cp.async.cg.shared.global [%1], [%3], 16;\n\t"
                    "cp.async.commit_group;\n\t"
                    :: "r"(dst + off_lo), "r"(dst + off_hi), "l"(src), "l"(src + 16));
            }

            float tt;
            tt = c0.x * wg0.x;
            tt = fmaf(c0.y, wg0.y, tt);
            tt = fmaf(c0.z, wg0.z, tt);
            tt = fmaf(c0.w, wg0.w, tt);
            tt = fmaf(c1.x, wg1.x, tt);
            tt = fmaf(c1.y, wg1.y, tt);
            tt = fmaf(c1.z, wg1.z, tt);
            tt = fmaf(c1.w, wg1.w, tt);
            #pragma unroll
            for (int o = 16; o; o >>= 1) tt += __shfl_xor_sync(0xffffffffu, tt, o);
            const float g = tt + bgv;

            const float mn    = fmaxf(m, g);
            const float scale = __expf(m - mn);
            const float e     = __expf(fmaf(pv, __logf(wc), g - mn));
            dnm = fmaf(dnm, scale, e);
            acc[0] = fmaf(acc[0], scale, e * c0.x);
            acc[1] = fmaf(acc[1], scale, e * c0.y);
            acc[2] = fmaf(acc[2], scale, e * c0.z);
            acc[3] = fmaf(acc[3], scale, e * c0.w);
            acc[4] = fmaf(acc[4], scale, e * c1.x);
            acc[5] = fmaf(acc[5], scale, e * c1.y);
            acc[6] = fmaf(acc[6], scale, e * c1.z);
            acc[7] = fmaf(acc[7], scale, e * c1.w);
            m  = mn;
            wc = wn;

            if (++slot_r == RING) slot_r = 0;
            if (++slot_i == RING) slot_i = 0;
        }

        const float inv = 1.f / (dnm + 1e-10f);
        float4 o0, o1;
        o0.x = acc[0] * inv; o0.y = acc[1] * inv; o0.z = acc[2] * inv; o0.w = acc[3] * inv;
        o1.x = acc[4] * inv; o1.y = acc[5] * inv; o1.z = acc[6] * inv; o1.w = acc[7] * inv;
        *reinterpret_cast<float4*>(arow)     = o0;
        *reinterpret_cast<float4*>(arow + 4) = o1;
        if (lane == 0) s_gsum[lr] = dnm * inv;
    }

    // drain remaining clamped groups before B buffers alias the rings
    asm volatile("cp.async.wait_group 0;" ::: "memory");
    __syncthreads();

    // ================= Phase 2: GEMM 64x256 tile =================
    // A: smem (broadcast loads). B = Wm streamed in 16-row chunks, double buffer.
    const uint32_t b_base = smem_u32 + RING_OFF;        // 2 x 16KB
    const int ty = t >> 5;                              // 0..7  -> rows ty*8+[0,8)
    const int tx = t & 31;                              // 0..31 -> cols tx*4, 128+tx*4

    // chunk loader: 4 x 16B per thread, coalesced
    const int ld_row  = t >> 6;                          // 0..3 (x4 rows per j)
    const int ld_col4 = t & 63;                          // 0..63

    // prologue: chunks 0 and 1
    #pragma unroll
    for (int c = 0; c < 2; ++c) {
        const uint32_t dst = b_base + c * 16384;
        #pragma unroll
        for (int j = 0; j < 4; ++j) {
            const int row = ld_row + j * 4;
            const char* src = reinterpret_cast<const char*>(
                Wm + (size_t)(c * 16 + row) * D + ld_col4 * 4);
            asm volatile(
                "cp.async.cg.shared.global [%0], [%1], 16;\n\t"
                :: "r"(dst + row * 1024 + ld_col4 * 16), "l"(src));
        }
        asm volatile("cp.async.commit_group;" ::: "memory");
    }

    unsigned long long acc2[8][4];
    #pragma unroll
    for (int i = 0; i < 8; ++i)
        #pragma unroll
        for (int j = 0; j < 4; ++j) acc2[i][j] = 0ull;

    const float* As_f = As;

    for (int c = 0; c < 16; ++c) {
        if (c < 14) asm volatile("cp.async.wait_group 1;" ::: "memory");
        else        asm volatile("cp.async.wait_group 0;" ::: "memory");
        __syncthreads();

        const int buf = c & 1;
        const uint32_t bb = b_base + buf * 16384;

        #pragma unroll
        for (int kk = 0; kk < 16; ++kk) {
            const int kg = c * 16 + kk;
            // A: broadcast loads (all lanes same address)
            unsigned long long a2[8];
            #pragma unroll
            for (int i = 0; i < 8; ++i) {
                const float av = As_f[(ty * 8 + i) * D + kg];
                PACK_DUP_F32X2(a2[i], av);
            }
            // B: two stride-4 float4 groups -> conflict-free LDS.128
            ulonglong2 blo, bhi;
            asm volatile("ld.shared.v4.f32 {%0,%1,%2,%3}, [%4];"
                : "=f"(((float2*)&blo)[0].x), "=f"(((float2*)&blo)[0].y),
                  "=f"(((float2*)&blo)[1].x), "=f"(((float2*)&blo)[1].y)
                : "r"(bb + kk * 1024 + tx * 16));
            asm volatile("ld.shared.v4.f32 {%0,%1,%2,%3}, [%4];"
                : "=f"(((float2*)&bhi)[0].x), "=f"(((float2*)&bhi)[0].y),
                  "=f"(((float2*)&bhi)[1].x), "=f"(((float2*)&bhi)[1].y)
                : "r"(bb + kk * 1024 + 512 + tx * 16));
            unsigned long long b2[4] = {blo.x, blo.y, bhi.x, bhi.y};

            #pragma unroll
            for (int i = 0; i < 8; ++i)
                #pragma unroll
                for (int j = 0; j < 4; ++j)
                    FMA_F32X2(acc2[i][j], a2[i], b2[j]);
        }
        __syncthreads();

        // issue chunk c+2 into this buffer
        if (c + 2 < 16) {
            const uint32_t dst = b_base + buf * 16384;
            #pragma unroll
            for (int j = 0; j < 4; ++j) {
                const int row = ld_row + j * 4;
                const char* src = reinterpret_cast<const char*>(
                    Wm + (size_t)((c + 2) * 16 + row) * D + ld_col4 * 4);
                asm volatile(
                    "cp.async.cg.shared.global [%0], [%1], 16;\n\t"
                    :: "r"(dst + row * 1024 + ld_col4 * 16), "l"(src));
            }
            asm volatile("cp.async.commit_group;" ::: "memory");
        }
    }

    // ---- epilogue: + gsum[m]*bm[n] ----
    const float4 bm_lo = *reinterpret_cast<const float4*>(&bm[tx * 4]);
    const float4 bm_hi = *reinterpret_cast<const float4*>(&bm[128 + tx * 4]);

    #pragma unroll
    for (int i = 0; i < 8; ++i) {
        const int m = seg0 + ty * 8 + i;
        if (m >= SS) break;
        const float gs = s_gsum[ty * 8 + i];
        float f[8];
        #pragma unroll
        for (int j = 0; j < 4; ++j) {
            unsigned int lo, hi;
            UNPACK_F32X2(lo, hi, acc2[i][j]);
            f[2 * j]     = __uint_as_float(lo);
            f[2 * j + 1] = __uint_as_float(hi);
        }
        float4 o0, o1;
        o0.x = fmaf(gs, bm_lo.x, f[0]);
        o0.y = fmaf(gs, bm_lo.y, f[1]);
        o0.z = fmaf(gs, bm_lo.z, f[2]);
        o0.w = fmaf(gs, bm_lo.w, f[3]);
        o1.x = fmaf(gs, bm_hi.x, f[4]);
        o1.y = fmaf(gs, bm_hi.y, f[5]);
        o1.z = fmaf(gs, bm_hi.z, f[6]);
        o1.w = fmaf(gs, bm_hi.w, f[7]);
        *reinterpret_cast<float4*>(&out[(size_t)m * D + tx * 4])       = o0;
        *reinterpret_cast<float4*>(&out[(size_t)m * D + 128 + tx * 4]) = o1;
    }
}

// ---------------------------------------------------------------------------
extern "C" void kernel_launch(void* const* d_in, const int* in_sizes, int n_in,
                              void* d_out, int out_size)
{
    const float* x   = (const float*)d_in[0];
    const float* w   = (const float*)d_in[1];
    const float* Wg  = (const float*)d_in[2];
    const float* bg  = (const float*)d_in[3];
    const float* Wm  = (const float*)d_in[4];
    const float* bm  = (const float*)d_in[5];
    const float* p   = (const float*)d_in[6];
    const int*   idx = (const int*)d_in[7];
    float* out = (float*)d_out;

    const int n = in_sizes[0] / D;   // 500000

    cudaFuncSetAttribute(fused_kernel, cudaFuncAttributeMaxDynamicSharedMemorySize,
                         SMEM_DYN);

    seg_offsets_kernel<<<(n + 255) / 256, 256>>>(idx, n);
    const int nblk = (SS + SEG_PER_CTA - 1) / SEG_PER_CTA;   // 313
    fused_kernel<<<nblk, 256, SMEM_DYN>>>(x, w, Wg, bg, Wm, bm, p, out);
}